// round 5
// baseline (speedup 1.0000x reference)
#include <cuda_runtime.h>
#include <cuda_bf16.h>
#include <math.h>

#define T_LEN 4096
#define DIM 768
#define HEADS 12
#define HD 64
#define RMS_EPS 1.1920928955078125e-07f
#define ATTN_SCALE 0.12f
#define BM 128
#define BN 64
#define QP 132   // Qs row stride (floats)
#define KP 68    // Ks/Vs row stride
#define PP 68    // Ps row stride

// ---------------- scratch ----------------
__device__ float g_qkv[T_LEN * 3 * DIM];          // [T][3*768]
__device__ float g_Qt[HEADS * HD * T_LEN];        // [h][d][t]  (transposed)
__device__ float g_Kt[HEADS * HD * T_LEN];        // [h][d][t]
__device__ float g_V [HEADS * T_LEN * HD];        // [h][t][d]
__device__ float g_Y [T_LEN * DIM];               // [t][h*64+d]

// ---------------- GEMM: C[M,N] = A[M,K] * B[N,K]^T ----------------
__global__ __launch_bounds__(256) void gemm_nt(const float* __restrict__ A,
                                               const float* __restrict__ B,
                                               float* __restrict__ C,
                                               int M, int N, int K) {
    __shared__ float As[16][128];
    __shared__ float Bs[16][128];
    const int tid = threadIdx.x;
    const int tx = tid & 15;
    const int ty = tid >> 4;
    const int row0 = blockIdx.y * 128;
    const int col0 = blockIdx.x * 128;

    float acc[8][8];
#pragma unroll
    for (int i = 0; i < 8; i++)
#pragma unroll
        for (int j = 0; j < 8; j++) acc[i][j] = 0.f;

    for (int k0 = 0; k0 < K; k0 += 16) {
#pragma unroll
        for (int i = 0; i < 2; i++) {
            int id = tid + i * 256;
            int r = id >> 2;
            int c = (id & 3) << 2;
            float4 a = *(const float4*)&A[(size_t)(row0 + r) * K + k0 + c];
            As[c + 0][r] = a.x; As[c + 1][r] = a.y;
            As[c + 2][r] = a.z; As[c + 3][r] = a.w;
            float4 b = *(const float4*)&B[(size_t)(col0 + r) * K + k0 + c];
            Bs[c + 0][r] = b.x; Bs[c + 1][r] = b.y;
            Bs[c + 2][r] = b.z; Bs[c + 3][r] = b.w;
        }
        __syncthreads();
#pragma unroll
        for (int k = 0; k < 16; k++) {
            float a[8], b[8];
            *(float4*)&a[0] = *(float4*)&As[k][ty * 8];
            *(float4*)&a[4] = *(float4*)&As[k][ty * 8 + 4];
            *(float4*)&b[0] = *(float4*)&Bs[k][tx * 8];
            *(float4*)&b[4] = *(float4*)&Bs[k][tx * 8 + 4];
#pragma unroll
            for (int i = 0; i < 8; i++)
#pragma unroll
                for (int j = 0; j < 8; j++) acc[i][j] = fmaf(a[i], b[j], acc[i][j]);
        }
        __syncthreads();
    }

#pragma unroll
    for (int i = 0; i < 8; i++) {
        float* cp = &C[(size_t)(row0 + ty * 8 + i) * N + col0 + tx * 8];
        *(float4*)&cp[0] = make_float4(acc[i][0], acc[i][1], acc[i][2], acc[i][3]);
        *(float4*)&cp[4] = make_float4(acc[i][4], acc[i][5], acc[i][6], acc[i][7]);
    }
}

// ---------------- prep: RMS + rotary; Q,K -> [h][d][t], V -> [h][t][d] ----------------
__global__ void prep_kernel(const float* __restrict__ qkv,
                            float* __restrict__ Qt, float* __restrict__ Kt,
                            float* __restrict__ V) {
    int gwarp = (blockIdx.x * blockDim.x + threadIdx.x) >> 5;
    int lane = threadIdx.x & 31;
    if (gwarp >= T_LEN * HEADS) return;
    int t = gwarp / HEADS;
    int h = gwarp % HEADS;
    const float* base = qkv + (size_t)t * (3 * DIM) + h * HD;

    float q1 = base[lane],            q2 = base[lane + 32];
    float k1 = base[DIM + lane],      k2 = base[DIM + lane + 32];
    float v1 = base[2 * DIM + lane],  v2 = base[2 * DIM + lane + 32];

    float sq = q1 * q1 + q2 * q2;
    float sk = k1 * k1 + k2 * k2;
#pragma unroll
    for (int o = 16; o > 0; o >>= 1) {
        sq += __shfl_xor_sync(0xffffffffu, sq, o);
        sk += __shfl_xor_sync(0xffffffffu, sk, o);
    }
    float rq = rsqrtf(sq * (1.f / 64.f) + RMS_EPS);
    float rk = rsqrtf(sk * (1.f / 64.f) + RMS_EPS);
    q1 *= rq; q2 *= rq;
    k1 *= rk; k2 *= rk;

    float freq = (lane < 16) ? exp2f((float)lane * (-10.0f / 15.0f)) : 0.0f;
    float theta = (float)t * freq;
    float s, c;
    sincosf(theta, &s, &c);

    float qy1 = q1 * c + q2 * s;
    float qy2 = -q1 * s + q2 * c;
    float ky1 = k1 * c + k2 * s;
    float ky2 = -k1 * s + k2 * c;

    size_t hb = (size_t)h * HD * T_LEN;
    Qt[hb + (size_t)lane * T_LEN + t] = qy1;
    Qt[hb + (size_t)(lane + 32) * T_LEN + t] = qy2;
    Kt[hb + (size_t)lane * T_LEN + t] = ky1;
    Kt[hb + (size_t)(lane + 32) * T_LEN + t] = ky2;
    size_t vo = ((size_t)h * T_LEN + t) * HD;
    V[vo + lane] = v1;  V[vo + lane + 32] = v2;
}

// ---------------- FlashAttention-2, conflict-free smem, 128x64 tiles ----------------
// 256 threads (16x16); thread owns 8 q-rows (ty*8) x 4 cols (tx*4).
__global__ __launch_bounds__(256, 2)
void flash_attn2(const float* __restrict__ Qt, const float* __restrict__ Kt,
                 const float* __restrict__ V, float* __restrict__ Y) {
    extern __shared__ float sm[];
    float* Qs = sm;                    // [64][QP]  Q^T: Qs[d][t]
    float* Ks = Qs + 64 * QP;          // [64][KP]  K^T: Ks[d][t]
    float* Vs = Ks + 64 * KP;          // [64][KP]  V:   Vs[j][d]
    float* Ps = Vs + 64 * KP;          // [128][PP] P:   Ps[q][j]

    const int h = blockIdx.y;
    const int qb = (gridDim.x - 1) - blockIdx.x;   // longest first
    const int q0 = qb * BM;
    const int tid = threadIdx.x;
    const int tx = tid & 15;
    const int ty = tid >> 4;

    const float* Qg = Qt + (size_t)h * HD * T_LEN;
    const float* Kg = Kt + (size_t)h * HD * T_LEN;
    const float* Vg = V + (size_t)h * T_LEN * HD;

    // stage Q^T tile [64 d][128 t] — coalesced loads, conflict-free stores
#pragma unroll
    for (int i = 0; i < 8; i++) {
        int id = tid + i * 256;        // 2048 float4 slots
        int d = id >> 5;
        int tg = (id & 31) << 2;
        float4 v = *(const float4*)&Qg[(size_t)d * T_LEN + q0 + tg];
        *(float4*)&Qs[d * QP + tg] = v;
    }

    float acco[8][4];
    float m_[8], l_[8];
#pragma unroll
    for (int i = 0; i < 8; i++) {
        m_[i] = -1e30f; l_[i] = 0.f;
#pragma unroll
        for (int j = 0; j < 4; j++) acco[i][j] = 0.f;
    }

    const int ntiles = 2 * qb + 2;
    for (int it = 0; it < ntiles; it++) {
        const int k0 = it * BN;
        __syncthreads();               // prev GEMM2 done with Ks/Vs/Ps
        // stage K^T [64 d][64 t] and V [64 t][64 d]
#pragma unroll
        for (int i = 0; i < 4; i++) {
            int id = tid + i * 256;    // 1024 float4 slots
            int r = id >> 4;
            int cg = (id & 15) << 2;
            float4 kv = *(const float4*)&Kg[(size_t)r * T_LEN + k0 + cg];
            *(float4*)&Ks[r * KP + cg] = kv;
            float4 vv = *(const float4*)&Vg[(size_t)(k0 + r) * HD + cg];
            *(float4*)&Vs[r * KP + cg] = vv;
        }
        __syncthreads();

        // GEMM1: S = Q @ K^T (k-dim = d)
        float accs[8][4];
#pragma unroll
        for (int i = 0; i < 8; i++)
#pragma unroll
            for (int j = 0; j < 4; j++) accs[i][j] = 0.f;

#pragma unroll 4
        for (int d = 0; d < 64; d++) {
            float a[8], b[4];
            *(float4*)&a[0] = *(float4*)&Qs[d * QP + ty * 8];
            *(float4*)&a[4] = *(float4*)&Qs[d * QP + ty * 8 + 4];
            *(float4*)&b[0] = *(float4*)&Ks[d * KP + tx * 4];
#pragma unroll
            for (int i = 0; i < 8; i++)
#pragma unroll
                for (int j = 0; j < 4; j++)
                    accs[i][j] = fmaf(a[i], b[j], accs[i][j]);
        }

        // scale + causal mask (only near-diagonal tiles)
        const bool need_mask = (k0 + BN > q0);
#pragma unroll
        for (int i = 0; i < 8; i++)
#pragma unroll
            for (int j = 0; j < 4; j++) {
                float s = accs[i][j] * ATTN_SCALE;
                if (need_mask && (k0 + tx * 4 + j > q0 + ty * 8 + i)) s = -1e30f;
                accs[i][j] = s;
            }

        // online softmax per row (16 tx lanes per row group)
#pragma unroll
        for (int i = 0; i < 8; i++) {
            float rm = fmaxf(fmaxf(accs[i][0], accs[i][1]), fmaxf(accs[i][2], accs[i][3]));
#pragma unroll
            for (int o = 8; o > 0; o >>= 1)
                rm = fmaxf(rm, __shfl_xor_sync(0xffffffffu, rm, o, 16));
            float newm = fmaxf(m_[i], rm);
            float corr = __expf(m_[i] - newm);
            m_[i] = newm;
            float rs = 0.f;
#pragma unroll
            for (int j = 0; j < 4; j++) {
                float p = __expf(accs[i][j] - newm);
                accs[i][j] = p;
                rs += p;
            }
#pragma unroll
            for (int o = 8; o > 0; o >>= 1)
                rs += __shfl_xor_sync(0xffffffffu, rs, o, 16);
            l_[i] = l_[i] * corr + rs;
#pragma unroll
            for (int j = 0; j < 4; j++) acco[i][j] *= corr;
            // store P natural: conflict-free float4
            *(float4*)&Ps[(ty * 8 + i) * PP + tx * 4] =
                make_float4(accs[i][0], accs[i][1], accs[i][2], accs[i][3]);
        }
        __syncthreads();   // Ps complete

        // GEMM2: O += P @ V (k-dim = j), j in steps of 4
#pragma unroll 2
        for (int j0 = 0; j0 < 64; j0 += 4) {
            float4 af[8];
#pragma unroll
            for (int i = 0; i < 8; i++)
                af[i] = *(float4*)&Ps[(ty * 8 + i) * PP + j0];
            float4 b0 = *(float4*)&Vs[(j0 + 0) * KP + tx * 4];
            float4 b1 = *(float4*)&Vs[(j0 + 1) * KP + tx * 4];
            float4 b2 = *(float4*)&Vs[(j0 + 2) * KP + tx * 4];
            float4 b3 = *(float4*)&Vs[(j0 + 3) * KP + tx * 4];
#pragma unroll
            for (int i = 0; i < 8; i++) {
                acco[i][0] = fmaf(af[i].x, b0.x, acco[i][0]);
                acco[i][1] = fmaf(af[i].x, b0.y, acco[i][1]);
                acco[i][2] = fmaf(af[i].x, b0.z, acco[i][2]);
                acco[i][3] = fmaf(af[i].x, b0.w, acco[i][3]);
                acco[i][0] = fmaf(af[i].y, b1.x, acco[i][0]);
                acco[i][1] = fmaf(af[i].y, b1.y, acco[i][1]);
                acco[i][2] = fmaf(af[i].y, b1.z, acco[i][2]);
                acco[i][3] = fmaf(af[i].y, b1.w, acco[i][3]);
                acco[i][0] = fmaf(af[i].z, b2.x, acco[i][0]);
                acco[i][1] = fmaf(af[i].z, b2.y, acco[i][1]);
                acco[i][2] = fmaf(af[i].z, b2.z, acco[i][2]);
                acco[i][3] = fmaf(af[i].z, b2.w, acco[i][3]);
                acco[i][0] = fmaf(af[i].w, b3.x, acco[i][0]);
                acco[i][1] = fmaf(af[i].w, b3.y, acco[i][1]);
                acco[i][2] = fmaf(af[i].w, b3.z, acco[i][2]);
                acco[i][3] = fmaf(af[i].w, b3.w, acco[i][3]);
            }
        }
    }

    // epilogue
#pragma unroll
    for (int i = 0; i < 8; i++) {
        float inv = 1.f / l_[i];
        float* yp = Y + (size_t)(q0 + ty * 8 + i) * DIM + h * HD + tx * 4;
        *(float4*)yp = make_float4(acco[i][0] * inv, acco[i][1] * inv,
                                   acco[i][2] * inv, acco[i][3] * inv);
    }
}

// ---------------- launch ----------------
extern "C" void kernel_launch(void* const* d_in, const int* in_sizes, int n_in,
                              void* d_out, int out_size) {
    const float* x = (const float*)d_in[0];
    const float* qkv_w = (const float*)d_in[1];
    const float* c_proj_w = (const float*)d_in[2];
    float* out = (float*)d_out;

    float *qkv, *Qt, *Kt, *Vb, *Yb;
    cudaGetSymbolAddress((void**)&qkv, g_qkv);
    cudaGetSymbolAddress((void**)&Qt, g_Qt);
    cudaGetSymbolAddress((void**)&Kt, g_Kt);
    cudaGetSymbolAddress((void**)&Vb, g_V);
    cudaGetSymbolAddress((void**)&Yb, g_Y);

    // 1) qkv = x @ qkv_w^T
    {
        dim3 grid(2304 / 128, T_LEN / 128);
        gemm_nt<<<grid, 256>>>(x, qkv_w, qkv, T_LEN, 2304, DIM);
    }
    // 2) RMS + rotary + transpose-relayout
    {
        int warps = T_LEN * HEADS;
        int threads = 256;
        int blocks = (warps * 32 + threads - 1) / threads;
        prep_kernel<<<blocks, threads>>>(qkv, Qt, Kt, Vb);
    }
    // 3) flash attention
    {
        const int smem_bytes = (64 * QP + 64 * KP + 64 * KP + 128 * PP) * (int)sizeof(float);
        cudaFuncSetAttribute(flash_attn2, cudaFuncAttributeMaxDynamicSharedMemorySize, smem_bytes);
        dim3 grid(T_LEN / BM, HEADS);
        flash_attn2<<<grid, 256, smem_bytes>>>(Qt, Kt, Vb, Yb);
    }
    // 4) out = Y @ c_proj_w^T
    {
        dim3 grid(DIM / 128, T_LEN / 128);
        gemm_nt<<<grid, 256>>>(Yb, c_proj_w, out, T_LEN, DIM, DIM);
    }
}

// round 8
// speedup vs baseline: 1.1993x; 1.1993x over previous
#include <cuda_runtime.h>
#include <cuda_bf16.h>
#include <math.h>
#include <stdint.h>

#define T_LEN 4096
#define DIM 768
#define HEADS 12
#define HD 64
#define RMS_EPS 1.1920928955078125e-07f
#define ATTN_SCALE 0.12f
#define BM 128
#define BN 64
#define QP 132
#define KP 68
#define PP 68

__device__ float g_qkv[T_LEN * 3 * DIM];
__device__ float g_Qt[HEADS * HD * T_LEN];
__device__ float g_Kt[HEADS * HD * T_LEN];
__device__ float g_V [HEADS * T_LEN * HD];
__device__ float g_Y [T_LEN * DIM];

// ---------------- mma.sync helper (base-ISA HMMA, works at compute_103) ----------------
__device__ __forceinline__ void mma16816(float* c, const uint32_t* a, const uint32_t* b) {
    asm volatile(
        "mma.sync.aligned.m16n8k16.row.col.f32.bf16.bf16.f32 "
        "{%0,%1,%2,%3}, {%4,%5,%6,%7}, {%8,%9}, {%0,%1,%2,%3};"
        : "+f"(c[0]), "+f"(c[1]), "+f"(c[2]), "+f"(c[3])
        : "r"(a[0]), "r"(a[1]), "r"(a[2]), "r"(a[3]), "r"(b[0]), "r"(b[1]));
}

__device__ __forceinline__ void split2(float x, float y, uint32_t& hi, uint32_t& lo) {
    __nv_bfloat162 h;
    h.x = __float2bfloat16_rn(x);
    h.y = __float2bfloat16_rn(y);
    __nv_bfloat162 l = __floats2bfloat162_rn(x - __bfloat162float(h.x),
                                             y - __bfloat162float(h.y));
    hi = *reinterpret_cast<uint32_t*>(&h);
    lo = *reinterpret_cast<uint32_t*>(&l);
}

// ================= mma GEMM: C[M,N] = A[M,K] * B[N,K]^T, bf16x3 split =================
// CTA 128x128, 256 thr = 8 warps (2m x 4n), warp tile m64n32, K-chunk 32 (2 k16 steps).
// Smem tiles stored in FRAGMENT order:
//  A: slot(mt 0..7, s 0..1, lane) = ((mt*2+s)*32+lane)*16B; within: a0..a3 words.
//  B: slot(nt 0..15, s 0..1, lane) = ((nt*2+s)*32+lane)*8B; within: b0,b1 words.
__global__ __launch_bounds__(256, 1) void gemm_mma(const float* __restrict__ A,
                                                   const float* __restrict__ B,
                                                   float* __restrict__ C,
                                                   int M, int N, int K) {
    __shared__ __align__(16) uint8_t sAh[8192];
    __shared__ __align__(16) uint8_t sAl[8192];
    __shared__ __align__(16) uint8_t sBh[8192];
    __shared__ __align__(16) uint8_t sBl[8192];

    const int tid = threadIdx.x;
    const int wid = tid >> 5;
    const int lane = tid & 31;
    const int row0 = blockIdx.y * 128;
    const int col0 = blockIdx.x * 128;

    // producer mapping: 2 threads per row, 4 float4 each (k = hf*16 + i*4)
    const int prow = tid >> 1;
    const int hf = tid & 1;
    const float* Ar = A + (size_t)(row0 + prow) * K;
    const float* Br = B + (size_t)(col0 + prow) * K;

    // A store bases (bytes)
    const int mt = prow >> 4, rr = prow & 15;
    const int ar = rr & 7, up = rr >> 3;
    const int aBase = ((mt * 2 + hf) * 32) * 16;
    // B store bases
    const int nt = prow >> 3, nn = prow & 7;
    const int bBase = ((nt * 2 + hf) * 32) * 8;

    float acc[4][4][4];
#pragma unroll
    for (int i = 0; i < 4; i++)
#pragma unroll
        for (int j = 0; j < 4; j++)
#pragma unroll
            for (int k = 0; k < 4; k++) acc[i][j][k] = 0.f;

    const int nch = K >> 5;
    float4 ra[4], rb[4];
#pragma unroll
    for (int i = 0; i < 4; i++) {
        int kc = hf * 16 + i * 4;
        ra[i] = *(const float4*)&Ar[kc];
        rb[i] = *(const float4*)&Br[kc];
    }

    const int wm = (wid & 1) * 4;   // A mtile base (x16 rows)
    const int wn = (wid >> 1) * 4;  // B ntile base (x8 cols)

    for (int ch = 0; ch < nch; ch++) {
#pragma unroll
        for (int i = 0; i < 4; i++) {
            // word slots: l = r*4 + (i&1)*2 + w ; a-word = up + 2*(i>>1)
            int la = aBase + (ar * 4 + (i & 1) * 2) * 16 + up * 4 + (i >> 1) * 8;
            uint32_t hi0, lo0, hi1, lo1;
            split2(ra[i].x, ra[i].y, hi0, lo0);
            split2(ra[i].z, ra[i].w, hi1, lo1);
            *(uint32_t*)(sAh + la) = hi0;
            *(uint32_t*)(sAl + la) = lo0;
            *(uint32_t*)(sAh + la + 16) = hi1;
            *(uint32_t*)(sAl + la + 16) = lo1;
            int lb = bBase + (nn * 4 + (i & 1) * 2) * 8 + (i >> 1) * 4;
            split2(rb[i].x, rb[i].y, hi0, lo0);
            split2(rb[i].z, rb[i].w, hi1, lo1);
            *(uint32_t*)(sBh + lb) = hi0;
            *(uint32_t*)(sBl + lb) = lo0;
            *(uint32_t*)(sBh + lb + 8) = hi1;
            *(uint32_t*)(sBl + lb + 8) = lo1;
        }
        if (ch + 1 < nch) {
            int cb = (ch + 1) * 32 + hf * 16;
#pragma unroll
            for (int i = 0; i < 4; i++) {
                ra[i] = *(const float4*)&Ar[cb + i * 4];
                rb[i] = *(const float4*)&Br[cb + i * 4];
            }
        }
        __syncthreads();

#pragma unroll
        for (int s = 0; s < 2; s++) {
            uint4 ah[4], al[4];
            uint2 bh[4], bl[4];
#pragma unroll
            for (int i = 0; i < 4; i++) {
                int off = (((wm + i) * 2 + s) * 32 + lane) * 16;
                ah[i] = *(const uint4*)(sAh + off);
                al[i] = *(const uint4*)(sAl + off);
            }
#pragma unroll
            for (int j = 0; j < 4; j++) {
                int off = (((wn + j) * 2 + s) * 32 + lane) * 8;
                bh[j] = *(const uint2*)(sBh + off);
                bl[j] = *(const uint2*)(sBl + off);
            }
#pragma unroll
            for (int i = 0; i < 4; i++)
#pragma unroll
                for (int j = 0; j < 4; j++) {
                    mma16816(acc[i][j], (uint32_t*)&ah[i], (uint32_t*)&bh[j]);
                    mma16816(acc[i][j], (uint32_t*)&ah[i], (uint32_t*)&bl[j]);
                    mma16816(acc[i][j], (uint32_t*)&al[i], (uint32_t*)&bh[j]);
                }
        }
        __syncthreads();
    }

    // epilogue: c0,c1 -> (row, col..col+1); c2,c3 -> (row+8, ...)
    const int erow = row0 + (wid & 1) * 64 + (lane >> 2);
    const int ecol = col0 + (wid >> 1) * 32 + (lane & 3) * 2;
#pragma unroll
    for (int i = 0; i < 4; i++)
#pragma unroll
        for (int j = 0; j < 4; j++) {
            float* p0 = &C[(size_t)(erow + i * 16) * N + ecol + j * 8];
            float* p1 = &C[(size_t)(erow + i * 16 + 8) * N + ecol + j * 8];
            *(float2*)p0 = make_float2(acc[i][j][0], acc[i][j][1]);
            *(float2*)p1 = make_float2(acc[i][j][2], acc[i][j][3]);
        }
}

// ---------------- prep ----------------
__global__ void prep_kernel(const float* __restrict__ qkv,
                            float* __restrict__ Qt, float* __restrict__ Kt,
                            float* __restrict__ V) {
    int gwarp = (blockIdx.x * blockDim.x + threadIdx.x) >> 5;
    int lane = threadIdx.x & 31;
    if (gwarp >= T_LEN * HEADS) return;
    int t = gwarp / HEADS;
    int h = gwarp % HEADS;
    const float* base = qkv + (size_t)t * (3 * DIM) + h * HD;

    float q1 = base[lane],            q2 = base[lane + 32];
    float k1 = base[DIM + lane],      k2 = base[DIM + lane + 32];
    float v1 = base[2 * DIM + lane],  v2 = base[2 * DIM + lane + 32];

    float sq = q1 * q1 + q2 * q2;
    float sk = k1 * k1 + k2 * k2;
#pragma unroll
    for (int o = 16; o > 0; o >>= 1) {
        sq += __shfl_xor_sync(0xffffffffu, sq, o);
        sk += __shfl_xor_sync(0xffffffffu, sk, o);
    }
    float rq = rsqrtf(sq * (1.f / 64.f) + RMS_EPS);
    float rk = rsqrtf(sk * (1.f / 64.f) + RMS_EPS);
    q1 *= rq; q2 *= rq;
    k1 *= rk; k2 *= rk;

    float freq = (lane < 16) ? exp2f((float)lane * (-10.0f / 15.0f)) : 0.0f;
    float theta = (float)t * freq;
    float s, c;
    sincosf(theta, &s, &c);

    float qy1 = q1 * c + q2 * s;
    float qy2 = -q1 * s + q2 * c;
    float ky1 = k1 * c + k2 * s;
    float ky2 = -k1 * s + k2 * c;

    size_t hb = (size_t)h * HD * T_LEN;
    Qt[hb + (size_t)lane * T_LEN + t] = qy1;
    Qt[hb + (size_t)(lane + 32) * T_LEN + t] = qy2;
    Kt[hb + (size_t)lane * T_LEN + t] = ky1;
    Kt[hb + (size_t)(lane + 32) * T_LEN + t] = ky2;
    size_t vo = ((size_t)h * T_LEN + t) * HD;
    V[vo + lane] = v1;  V[vo + lane + 32] = v2;
}

// ---------------- FlashAttention-2 (unchanged, fp32 SIMT) ----------------
__global__ __launch_bounds__(256, 2)
void flash_attn2(const float* __restrict__ Qt, const float* __restrict__ Kt,
                 const float* __restrict__ V, float* __restrict__ Y) {
    extern __shared__ float sm[];
    float* Qs = sm;
    float* Ks = Qs + 64 * QP;
    float* Vs = Ks + 64 * KP;
    float* Ps = Vs + 64 * KP;

    const int h = blockIdx.y;
    const int qb = (gridDim.x - 1) - blockIdx.x;
    const int q0 = qb * BM;
    const int tid = threadIdx.x;
    const int tx = tid & 15;
    const int ty = tid >> 4;

    const float* Qg = Qt + (size_t)h * HD * T_LEN;
    const float* Kg = Kt + (size_t)h * HD * T_LEN;
    const float* Vg = V + (size_t)h * T_LEN * HD;

#pragma unroll
    for (int i = 0; i < 8; i++) {
        int id = tid + i * 256;
        int d = id >> 5;
        int tg = (id & 31) << 2;
        *(float4*)&Qs[d * QP + tg] = *(const float4*)&Qg[(size_t)d * T_LEN + q0 + tg];
    }

    float acco[8][4];
    float m_[8], l_[8];
#pragma unroll
    for (int i = 0; i < 8; i++) {
        m_[i] = -1e30f; l_[i] = 0.f;
#pragma unroll
        for (int j = 0; j < 4; j++) acco[i][j] = 0.f;
    }

    const int ntiles = 2 * qb + 2;
    for (int it = 0; it < ntiles; it++) {
        const int k0 = it * BN;
        __syncthreads();
#pragma unroll
        for (int i = 0; i < 4; i++) {
            int id = tid + i * 256;
            int r = id >> 4;
            int cg = (id & 15) << 2;
            *(float4*)&Ks[r * KP + cg] = *(const float4*)&Kg[(size_t)r * T_LEN + k0 + cg];
            *(float4*)&Vs[r * KP + cg] = *(const float4*)&Vg[(size_t)(k0 + r) * HD + cg];
        }
        __syncthreads();

        float accs[8][4];
#pragma unroll
        for (int i = 0; i < 8; i++)
#pragma unroll
            for (int j = 0; j < 4; j++) accs[i][j] = 0.f;

#pragma unroll 4
        for (int d = 0; d < 64; d++) {
            float a[8], b[4];
            *(float4*)&a[0] = *(float4*)&Qs[d * QP + ty * 8];
            *(float4*)&a[4] = *(float4*)&Qs[d * QP + ty * 8 + 4];
            *(float4*)&b[0] = *(float4*)&Ks[d * KP + tx * 4];
#pragma unroll
            for (int i = 0; i < 8; i++)
#pragma unroll
                for (int j = 0; j < 4; j++)
                    accs[i][j] = fmaf(a[i], b[j], accs[i][j]);
        }

        const bool need_mask = (k0 + BN > q0);
#pragma unroll
        for (int i = 0; i < 8; i++)
#pragma unroll
            for (int j = 0; j < 4; j++) {
                float s = accs[i][j] * ATTN_SCALE;
                if (need_mask && (k0 + tx * 4 + j > q0 + ty * 8 + i)) s = -1e30f;
                accs[i][j] = s;
            }

#pragma unroll
        for (int i = 0; i < 8; i++) {
            float rm = fmaxf(fmaxf(accs[i][0], accs[i][1]), fmaxf(accs[i][2], accs[i][3]));
#pragma unroll
            for (int o = 8; o > 0; o >>= 1)
                rm = fmaxf(rm, __shfl_xor_sync(0xffffffffu, rm, o, 16));
            float newm = fmaxf(m_[i], rm);
            float corr = __expf(m_[i] - newm);
            m_[i] = newm;
            float rs = 0.f;
#pragma unroll
            for (int j = 0; j < 4; j++) {
                float p = __expf(accs[i][j] - newm);
                accs[i][j] = p;
                rs += p;
            }
#pragma unroll
            for (int o = 8; o > 0; o >>= 1)
                rs += __shfl_xor_sync(0xffffffffu, rs, o, 16);
            l_[i] = l_[i] * corr + rs;
#pragma unroll
            for (int j = 0; j < 4; j++) acco[i][j] *= corr;
            *(float4*)&Ps[(ty * 8 + i) * PP + tx * 4] =
                make_float4(accs[i][0], accs[i][1], accs[i][2], accs[i][3]);
        }
        __syncthreads();

#pragma unroll 2
        for (int j0 = 0; j0 < 64; j0 += 4) {
            float4 af[8];
#pragma unroll
            for (int i = 0; i < 8; i++)
                af[i] = *(float4*)&Ps[(ty * 8 + i) * PP + j0];
            float4 b0 = *(float4*)&Vs[(j0 + 0) * KP + tx * 4];
            float4 b1 = *(float4*)&Vs[(j0 + 1) * KP + tx * 4];
            float4 b2 = *(float4*)&Vs[(j0 + 2) * KP + tx * 4];
            float4 b3 = *(float4*)&Vs[(j0 + 3) * KP + tx * 4];
#pragma unroll
            for (int i = 0; i < 8; i++) {
                acco[i][0] = fmaf(af[i].x, b0.x, acco[i][0]);
                acco[i][1] = fmaf(af[i].x, b0.y, acco[i][1]);
                acco[i][2] = fmaf(af[i].x, b0.z, acco[i][2]);
                acco[i][3] = fmaf(af[i].x, b0.w, acco[i][3]);
                acco[i][0] = fmaf(af[i].y, b1.x, acco[i][0]);
                acco[i][1] = fmaf(af[i].y, b1.y, acco[i][1]);
                acco[i][2] = fmaf(af[i].y, b1.z, acco[i][2]);
                acco[i][3] = fmaf(af[i].y, b1.w, acco[i][3]);
                acco[i][0] = fmaf(af[i].z, b2.x, acco[i][0]);
                acco[i][1] = fmaf(af[i].z, b2.y, acco[i][1]);
                acco[i][2] = fmaf(af[i].z, b2.z, acco[i][2]);
                acco[i][3] = fmaf(af[i].z, b2.w, acco[i][3]);
                acco[i][0] = fmaf(af[i].w, b3.x, acco[i][0]);
                acco[i][1] = fmaf(af[i].w, b3.y, acco[i][1]);
                acco[i][2] = fmaf(af[i].w, b3.z, acco[i][2]);
                acco[i][3] = fmaf(af[i].w, b3.w, acco[i][3]);
            }
        }
    }

#pragma unroll
    for (int i = 0; i < 8; i++) {
        float inv = 1.f / l_[i];
        float* yp = Y + (size_t)(q0 + ty * 8 + i) * DIM + h * HD + tx * 4;
        *(float4*)yp = make_float4(acco[i][0] * inv, acco[i][1] * inv,
                                   acco[i][2] * inv, acco[i][3] * inv);
    }
}

// ---------------- launch ----------------
extern "C" void kernel_launch(void* const* d_in, const int* in_sizes, int n_in,
                              void* d_out, int out_size) {
    const float* x = (const float*)d_in[0];
    const float* qkv_w = (const float*)d_in[1];
    const float* c_proj_w = (const float*)d_in[2];
    float* out = (float*)d_out;

    float *qkv, *Qt, *Kt, *Vb, *Yb;
    cudaGetSymbolAddress((void**)&qkv, g_qkv);
    cudaGetSymbolAddress((void**)&Qt, g_Qt);
    cudaGetSymbolAddress((void**)&Kt, g_Kt);
    cudaGetSymbolAddress((void**)&Vb, g_V);
    cudaGetSymbolAddress((void**)&Yb, g_Y);

    // 1) qkv = x @ qkv_w^T  (mma.sync bf16x3)
    {
        dim3 grid(2304 / 128, T_LEN / 128);
        gemm_mma<<<grid, 256>>>(x, qkv_w, qkv, T_LEN, 2304, DIM);
    }
    // 2) RMS + rotary + relayout
    {
        int warps = T_LEN * HEADS;
        int blocks = (warps * 32 + 255) / 256;
        prep_kernel<<<blocks, 256>>>(qkv, Qt, Kt, Vb);
    }
    // 3) flash attention (SIMT fp32)
    {
        const int smem_bytes = (64 * QP + 64 * KP + 64 * KP + 128 * PP) * (int)sizeof(float);
        cudaFuncSetAttribute(flash_attn2, cudaFuncAttributeMaxDynamicSharedMemorySize, smem_bytes);
        dim3 grid(T_LEN / BM, HEADS);
        flash_attn2<<<grid, 256, smem_bytes>>>(Qt, Kt, Vb, Yb);
    }
    // 4) out = Y @ c_proj_w^T  (mma.sync bf16x3)
    {
        dim3 grid(DIM / 128, T_LEN / 128);
        gemm_mma<<<grid, 256>>>(Yb, c_proj_w, out, T_LEN, DIM, DIM);
    }
}

// round 10
// speedup vs baseline: 2.0628x; 1.7200x over previous
#include <cuda_runtime.h>
#include <cuda_bf16.h>
#include <math.h>
#include <stdint.h>

#define T_LEN 4096
#define DIM 768
#define HEADS 12
#define HD 64
#define RMS_EPS 1.1920928955078125e-07f
#define ATTN_SCALE 0.12f

__device__ float g_qkv[T_LEN * 3 * DIM];
__device__ float g_Y [T_LEN * DIM];
__device__ __nv_bfloat16 g_Qh[HEADS * T_LEN * HD];
__device__ __nv_bfloat16 g_Ql[HEADS * T_LEN * HD];
__device__ __nv_bfloat16 g_Kh[HEADS * T_LEN * HD];
__device__ __nv_bfloat16 g_Kl[HEADS * T_LEN * HD];
__device__ __nv_bfloat16 g_Vh[HEADS * T_LEN * HD];
__device__ __nv_bfloat16 g_Vl[HEADS * T_LEN * HD];

// ---------------- mma.sync (base-ISA HMMA) ----------------
__device__ __forceinline__ void mma16816(float* c, const uint32_t* a, const uint32_t* b) {
    asm volatile(
        "mma.sync.aligned.m16n8k16.row.col.f32.bf16.bf16.f32 "
        "{%0,%1,%2,%3}, {%4,%5,%6,%7}, {%8,%9}, {%0,%1,%2,%3};"
        : "+f"(c[0]), "+f"(c[1]), "+f"(c[2]), "+f"(c[3])
        : "r"(a[0]), "r"(a[1]), "r"(a[2]), "r"(a[3]), "r"(b[0]), "r"(b[1]));
}

__device__ __forceinline__ void split2(float x, float y, uint32_t& hi, uint32_t& lo) {
    __nv_bfloat162 h;
    h.x = __float2bfloat16_rn(x);
    h.y = __float2bfloat16_rn(y);
    __nv_bfloat162 l = __floats2bfloat162_rn(x - __bfloat162float(h.x),
                                             y - __bfloat162float(h.y));
    hi = *reinterpret_cast<uint32_t*>(&h);
    lo = *reinterpret_cast<uint32_t*>(&l);
}

// ================= dense GEMM (unchanged, proven) =================
__global__ __launch_bounds__(256, 1) void gemm_mma(const float* __restrict__ A,
                                                   const float* __restrict__ B,
                                                   float* __restrict__ C,
                                                   int M, int N, int K) {
    __shared__ __align__(16) uint8_t sAh[8192];
    __shared__ __align__(16) uint8_t sAl[8192];
    __shared__ __align__(16) uint8_t sBh[8192];
    __shared__ __align__(16) uint8_t sBl[8192];

    const int tid = threadIdx.x;
    const int wid = tid >> 5;
    const int lane = tid & 31;
    const int row0 = blockIdx.y * 128;
    const int col0 = blockIdx.x * 128;

    const int prow = tid >> 1;
    const int hf = tid & 1;
    const float* Ar = A + (size_t)(row0 + prow) * K;
    const float* Br = B + (size_t)(col0 + prow) * K;

    const int mt = prow >> 4, rr = prow & 15;
    const int ar = rr & 7, up = rr >> 3;
    const int aBase = ((mt * 2 + hf) * 32) * 16;
    const int nt = prow >> 3, nn = prow & 7;
    const int bBase = ((nt * 2 + hf) * 32) * 8;

    float acc[4][4][4];
#pragma unroll
    for (int i = 0; i < 4; i++)
#pragma unroll
        for (int j = 0; j < 4; j++)
#pragma unroll
            for (int k = 0; k < 4; k++) acc[i][j][k] = 0.f;

    const int nch = K >> 5;
    float4 ra[4], rb[4];
#pragma unroll
    for (int i = 0; i < 4; i++) {
        int kc = hf * 16 + i * 4;
        ra[i] = *(const float4*)&Ar[kc];
        rb[i] = *(const float4*)&Br[kc];
    }

    const int wm = (wid & 1) * 4;
    const int wn = (wid >> 1) * 4;

    for (int ch = 0; ch < nch; ch++) {
#pragma unroll
        for (int i = 0; i < 4; i++) {
            int la = aBase + (ar * 4 + (i & 1) * 2) * 16 + up * 4 + (i >> 1) * 8;
            uint32_t hi0, lo0, hi1, lo1;
            split2(ra[i].x, ra[i].y, hi0, lo0);
            split2(ra[i].z, ra[i].w, hi1, lo1);
            *(uint32_t*)(sAh + la) = hi0;
            *(uint32_t*)(sAl + la) = lo0;
            *(uint32_t*)(sAh + la + 16) = hi1;
            *(uint32_t*)(sAl + la + 16) = lo1;
            int lb = bBase + (nn * 4 + (i & 1) * 2) * 8 + (i >> 1) * 4;
            split2(rb[i].x, rb[i].y, hi0, lo0);
            split2(rb[i].z, rb[i].w, hi1, lo1);
            *(uint32_t*)(sBh + lb) = hi0;
            *(uint32_t*)(sBl + lb) = lo0;
            *(uint32_t*)(sBh + lb + 8) = hi1;
            *(uint32_t*)(sBl + lb + 8) = lo1;
        }
        if (ch + 1 < nch) {
            int cb = (ch + 1) * 32 + hf * 16;
#pragma unroll
            for (int i = 0; i < 4; i++) {
                ra[i] = *(const float4*)&Ar[cb + i * 4];
                rb[i] = *(const float4*)&Br[cb + i * 4];
            }
        }
        __syncthreads();

#pragma unroll
        for (int s = 0; s < 2; s++) {
            uint4 ah[4], al[4];
            uint2 bh[4], bl[4];
#pragma unroll
            for (int i = 0; i < 4; i++) {
                int off = (((wm + i) * 2 + s) * 32 + lane) * 16;
                ah[i] = *(const uint4*)(sAh + off);
                al[i] = *(const uint4*)(sAl + off);
            }
#pragma unroll
            for (int j = 0; j < 4; j++) {
                int off = (((wn + j) * 2 + s) * 32 + lane) * 8;
                bh[j] = *(const uint2*)(sBh + off);
                bl[j] = *(const uint2*)(sBl + off);
            }
#pragma unroll
            for (int i = 0; i < 4; i++)
#pragma unroll
                for (int j = 0; j < 4; j++) {
                    mma16816(acc[i][j], (uint32_t*)&ah[i], (uint32_t*)&bh[j]);
                    mma16816(acc[i][j], (uint32_t*)&ah[i], (uint32_t*)&bl[j]);
                    mma16816(acc[i][j], (uint32_t*)&al[i], (uint32_t*)&bh[j]);
                }
        }
        __syncthreads();
    }

    const int erow = row0 + (wid & 1) * 64 + (lane >> 2);
    const int ecol = col0 + (wid >> 1) * 32 + (lane & 3) * 2;
#pragma unroll
    for (int i = 0; i < 4; i++)
#pragma unroll
        for (int j = 0; j < 4; j++) {
            float* p0 = &C[(size_t)(erow + i * 16) * N + ecol + j * 8];
            float* p1 = &C[(size_t)(erow + i * 16 + 8) * N + ecol + j * 8];
            *(float2*)p0 = make_float2(acc[i][j][0], acc[i][j][1]);
            *(float2*)p1 = make_float2(acc[i][j][2], acc[i][j][3]);
        }
}

// ---------------- prep: RMS + rotary -> bf16 hi/lo [h][t][d] ----------------
__global__ void prep_kernel(const float* __restrict__ qkv) {
    int gwarp = (blockIdx.x * blockDim.x + threadIdx.x) >> 5;
    int lane = threadIdx.x & 31;
    if (gwarp >= T_LEN * HEADS) return;
    int t = gwarp / HEADS;
    int h = gwarp % HEADS;
    const float* base = qkv + (size_t)t * (3 * DIM) + h * HD;

    float q1 = base[lane],            q2 = base[lane + 32];
    float k1 = base[DIM + lane],      k2 = base[DIM + lane + 32];
    float v1 = base[2 * DIM + lane],  v2 = base[2 * DIM + lane + 32];

    float sq = q1 * q1 + q2 * q2;
    float sk = k1 * k1 + k2 * k2;
#pragma unroll
    for (int o = 16; o > 0; o >>= 1) {
        sq += __shfl_xor_sync(0xffffffffu, sq, o);
        sk += __shfl_xor_sync(0xffffffffu, sk, o);
    }
    float rq = rsqrtf(sq * (1.f / 64.f) + RMS_EPS);
    float rk = rsqrtf(sk * (1.f / 64.f) + RMS_EPS);
    q1 *= rq; q2 *= rq;
    k1 *= rk; k2 *= rk;

    float freq = (lane < 16) ? exp2f((float)lane * (-10.0f / 15.0f)) : 0.0f;
    float theta = (float)t * freq;
    float s, c;
    sincosf(theta, &s, &c);

    float qa = q1 * c + q2 * s;
    float qb = -q1 * s + q2 * c;
    float ka = k1 * c + k2 * s;
    float kb = -k1 * s + k2 * c;

    size_t o0 = ((size_t)h * T_LEN + t) * HD + lane;
    size_t o1 = o0 + 32;
#define SPLIT_ST(arrH, arrL, idx, val) do { \
        __nv_bfloat16 _h = __float2bfloat16_rn(val); \
        arrH[idx] = _h; \
        arrL[idx] = __float2bfloat16_rn((val) - __bfloat162float(_h)); \
    } while (0)
    SPLIT_ST(g_Qh, g_Ql, o0, qa); SPLIT_ST(g_Qh, g_Ql, o1, qb);
    SPLIT_ST(g_Kh, g_Kl, o0, ka); SPLIT_ST(g_Kh, g_Kl, o1, kb);
    SPLIT_ST(g_Vh, g_Vl, o0, v1); SPLIT_ST(g_Vh, g_Vl, o1, v2);
#undef SPLIT_ST
}

// ---------------- flash attention via mma.sync, static-max softmax ----------------
// CTA: 128 q-rows, 8 warps (warp = m16 x n64 strip), key tiles of 64.
// smem (64KB): Qh 16K | Ql 16K | Kh 8K | Kl 8K | Vh 8K | Vl 8K, fragment-order slots.
__global__ __launch_bounds__(256, 2)
void flash_mma(float* __restrict__ Y) {
    extern __shared__ uint8_t sm8[];
    uint32_t* sQh = (uint32_t*)(sm8);
    uint32_t* sQl = (uint32_t*)(sm8 + 16384);
    uint32_t* sKh = (uint32_t*)(sm8 + 32768);
    uint32_t* sKl = (uint32_t*)(sm8 + 40960);
    uint32_t* sVh = (uint32_t*)(sm8 + 49152);
    uint32_t* sVl = (uint32_t*)(sm8 + 57344);

    const int h = blockIdx.y;
    const int qb = (gridDim.x - 1) - blockIdx.x;   // heaviest first
    const int q0 = qb * 128;
    const int tid = threadIdx.x;
    const int w = tid >> 5;
    const int lane = tid & 31;
    const int gid = lane >> 2;
    const int tig = lane & 3;

    const uint32_t* gQh = (const uint32_t*)g_Qh + ((size_t)h * T_LEN + q0) * 32;
    const uint32_t* gQl = (const uint32_t*)g_Ql + ((size_t)h * T_LEN + q0) * 32;
    const uint32_t* gKh = (const uint32_t*)g_Kh + (size_t)h * T_LEN * 32;
    const uint32_t* gKl = (const uint32_t*)g_Kl + (size_t)h * T_LEN * 32;
    const uint32_t* gVh = (const uint32_t*)g_Vh + (size_t)h * T_LEN * 32;
    const uint32_t* gVl = (const uint32_t*)g_Vl + (size_t)h * T_LEN * 32;

    // ---- stage Q into A-fragment slots (once per block) ----
    {
        const int t = tid >> 1;
        const int mt = t >> 4, rr = t & 15;
        const int g8 = rr & 7, wb = rr >> 3;
#pragma unroll
        for (int jj = 0; jj < 2; jj++) {
            int dw0 = (tid & 1) * 16 + jj * 8;
#pragma unroll
            for (int half = 0; half < 2; half++) {
                uint4 qh4 = *(const uint4*)(gQh + (size_t)t * 32 + dw0 + half * 4);
                uint4 ql4 = *(const uint4*)(gQl + (size_t)t * 32 + dw0 + half * 4);
#pragma unroll
                for (int c = 0; c < 4; c++) {
                    int dw = dw0 + half * 4 + c;
                    int s = dw >> 3, tg = dw & 3, hi4 = (dw >> 2) & 1;
                    int addr = ((mt * 4 + s) * 32 + g8 * 4 + tg) * 4 + wb + 2 * hi4;
                    sQh[addr] = ((const uint32_t*)&qh4)[c];
                    sQl[addr] = ((const uint32_t*)&ql4)[c];
                }
            }
        }
    }

    float O[8][4];
#pragma unroll
    for (int i = 0; i < 8; i++)
#pragma unroll
        for (int j = 0; j < 4; j++) O[i][j] = 0.f;
    float l0 = 0.f, l1 = 0.f;

    const int ntiles = 2 * qb + 2;
    for (int it = 0; it < ntiles; it++) {
        const int k0 = it * 64;
        __syncthreads();
        // ---- stage K (B-frags, k-dim = d: contiguous pairs) ----
        {
            const int t = tid >> 2, s = tid & 3;
            const int nt = t >> 3, g8 = t & 7;
            const uint32_t* srcH = gKh + (size_t)(k0 + t) * 32 + s * 8;
            const uint32_t* srcL = gKl + (size_t)(k0 + t) * 32 + s * 8;
            uint4 a0 = *(const uint4*)srcH;
            uint4 a1 = *(const uint4*)(srcH + 4);
            uint32_t* dst = sKh + ((nt * 4 + s) * 32 + g8 * 4) * 2;
            dst[0] = a0.x; dst[1] = a1.x; dst[2] = a0.y; dst[3] = a1.y;
            dst[4] = a0.z; dst[5] = a1.z; dst[6] = a0.w; dst[7] = a1.w;
            uint4 b0 = *(const uint4*)srcL;
            uint4 b1 = *(const uint4*)(srcL + 4);
            dst = sKl + ((nt * 4 + s) * 32 + g8 * 4) * 2;
            dst[0] = b0.x; dst[1] = b1.x; dst[2] = b0.y; dst[3] = b1.y;
            dst[4] = b0.z; dst[5] = b1.z; dst[6] = b0.w; dst[7] = b1.w;
        }
        // ---- stage V (B-frags, k-dim = j: cross-row pairs via PRMT) ----
        {
            const int jp = tid >> 3, dwb = (tid & 7) * 4;
            const int s = jp >> 3, qq = jp & 7;
            const int word = qq >> 2, tg = qq & 3;
            uint4 v0 = *(const uint4*)(gVh + (size_t)(k0 + 2 * jp) * 32 + dwb);
            uint4 v1 = *(const uint4*)(gVh + (size_t)(k0 + 2 * jp + 1) * 32 + dwb);
            uint4 u0 = *(const uint4*)(gVl + (size_t)(k0 + 2 * jp) * 32 + dwb);
            uint4 u1 = *(const uint4*)(gVl + (size_t)(k0 + 2 * jp + 1) * 32 + dwb);
#pragma unroll
            for (int c = 0; c < 4; c++) {
                int dw = dwb + c;
                int d0 = 2 * dw;
                int nt = d0 >> 3, g0 = d0 & 7;
                uint32_t base = ((nt * 4 + s) * 32 + g0 * 4 + tg) * 2 + word;
                uint32_t w0 = ((const uint32_t*)&v0)[c], w1 = ((const uint32_t*)&v1)[c];
                sVh[base] = __byte_perm(w0, w1, 0x5410);
                sVh[base + 8] = __byte_perm(w0, w1, 0x7632);
                w0 = ((const uint32_t*)&u0)[c]; w1 = ((const uint32_t*)&u1)[c];
                sVl[base] = __byte_perm(w0, w1, 0x5410);
                sVl[base + 8] = __byte_perm(w0, w1, 0x7632);
            }
        }
        __syncthreads();

        const int rbase = q0 + w * 16;
        if (k0 > rbase + 15) continue;   // warp fully above diagonal

        // ---- S = Q K^T (bf16x3) ----
        float S[8][4];
#pragma unroll
        for (int i = 0; i < 8; i++)
#pragma unroll
            for (int j = 0; j < 4; j++) S[i][j] = 0.f;
#pragma unroll
        for (int s = 0; s < 4; s++) {
            uint4 ah = *(const uint4*)(sQh + ((w * 4 + s) * 32 + lane) * 4);
            uint4 al = *(const uint4*)(sQl + ((w * 4 + s) * 32 + lane) * 4);
#pragma unroll
            for (int nt = 0; nt < 8; nt++) {
                uint2 bh = *(const uint2*)(sKh + ((nt * 4 + s) * 32 + lane) * 2);
                uint2 bl = *(const uint2*)(sKl + ((nt * 4 + s) * 32 + lane) * 2);
                mma16816(S[nt], (const uint32_t*)&ah, (const uint32_t*)&bh);
                mma16816(S[nt], (const uint32_t*)&ah, (const uint32_t*)&bl);
                mma16816(S[nt], (const uint32_t*)&al, (const uint32_t*)&bh);
            }
        }

        // ---- exp (static max: |s| <= 7.68) + mask + partial row sums ----
        const bool needmask = (k0 + 63 > rbase);
        const int r0 = rbase + gid, r1 = r0 + 8;
#pragma unroll
        for (int nt = 0; nt < 8; nt++) {
            int c0 = k0 + nt * 8 + tig * 2;
            float p0 = __expf(ATTN_SCALE * S[nt][0]);
            float p1 = __expf(ATTN_SCALE * S[nt][1]);
            float p2 = __expf(ATTN_SCALE * S[nt][2]);
            float p3 = __expf(ATTN_SCALE * S[nt][3]);
            if (needmask) {
                if (c0 > r0) p0 = 0.f;
                if (c0 + 1 > r0) p1 = 0.f;
                if (c0 > r1) p2 = 0.f;
                if (c0 + 1 > r1) p3 = 0.f;
            }
            l0 += p0 + p1;
            l1 += p2 + p3;
            S[nt][0] = p0; S[nt][1] = p1; S[nt][2] = p2; S[nt][3] = p3;
        }

        // ---- O += P V (P packed from S registers; bf16x3) ----
#pragma unroll
        for (int s = 0; s < 4; s++) {
            uint32_t Ph[4], Pl[4];
            split2(S[2 * s][0], S[2 * s][1], Ph[0], Pl[0]);
            split2(S[2 * s][2], S[2 * s][3], Ph[1], Pl[1]);
            split2(S[2 * s + 1][0], S[2 * s + 1][1], Ph[2], Pl[2]);
            split2(S[2 * s + 1][2], S[2 * s + 1][3], Ph[3], Pl[3]);
#pragma unroll
            for (int nt = 0; nt < 8; nt++) {
                uint2 bh = *(const uint2*)(sVh + ((nt * 4 + s) * 32 + lane) * 2);
                uint2 bl = *(const uint2*)(sVl + ((nt * 4 + s) * 32 + lane) * 2);
                mma16816(O[nt], Ph, (const uint32_t*)&bh);
                mma16816(O[nt], Ph, (const uint32_t*)&bl);
                mma16816(O[nt], Pl, (const uint32_t*)&bh);
            }
        }
    }

    // ---- final: reduce l across the 4 lanes sharing each row, normalize, store ----
    l0 += __shfl_xor_sync(0xffffffffu, l0, 1, 4);
    l0 += __shfl_xor_sync(0xffffffffu, l0, 2, 4);
    l1 += __shfl_xor_sync(0xffffffffu, l1, 1, 4);
    l1 += __shfl_xor_sync(0xffffffffu, l1, 2, 4);
    const float inv0 = 1.f / l0, inv1 = 1.f / l1;
    const int r0 = q0 + w * 16 + gid;
#pragma unroll
    for (int nt = 0; nt < 8; nt++) {
        int col = h * HD + nt * 8 + tig * 2;
        *(float2*)&Y[(size_t)r0 * DIM + col] = make_float2(O[nt][0] * inv0, O[nt][1] * inv0);
        *(float2*)&Y[(size_t)(r0 + 8) * DIM + col] = make_float2(O[nt][2] * inv1, O[nt][3] * inv1);
    }
}

// ---------------- launch ----------------
extern "C" void kernel_launch(void* const* d_in, const int* in_sizes, int n_in,
                              void* d_out, int out_size) {
    const float* x = (const float*)d_in[0];
    const float* qkv_w = (const float*)d_in[1];
    const float* c_proj_w = (const float*)d_in[2];
    float* out = (float*)d_out;

    float *qkv, *Yb;
    cudaGetSymbolAddress((void**)&qkv, g_qkv);
    cudaGetSymbolAddress((void**)&Yb, g_Y);

    // 1) qkv = x @ qkv_w^T
    {
        dim3 grid(2304 / 128, T_LEN / 128);
        gemm_mma<<<grid, 256>>>(x, qkv_w, qkv, T_LEN, 2304, DIM);
    }
    // 2) RMS + rotary -> bf16 hi/lo
    {
        int warps = T_LEN * HEADS;
        int blocks = (warps * 32 + 255) / 256;
        prep_kernel<<<blocks, 256>>>(qkv);
    }
    // 3) flash attention (mma.sync bf16x3, static-max softmax)
    {
        cudaFuncSetAttribute(flash_mma, cudaFuncAttributeMaxDynamicSharedMemorySize, 65536);
        dim3 grid(T_LEN / 128, HEADS);
        flash_mma<<<grid, 256, 65536>>>(Yb);
    }
    // 4) out = Y @ c_proj_w^T
    {
        dim3 grid(DIM / 128, T_LEN / 128);
        gemm_mma<<<grid, 256>>>(Yb, c_proj_w, out, T_LEN, DIM, DIM);
    }
}